// round 2
// baseline (speedup 1.0000x reference)
#include <cuda_runtime.h>
#include <cuda_bf16.h>
#include <cstdint>

// Problem constants
#define BB 32
#define NN 1024
#define IN_DIM 64
#define HID 128
#define OUTD 64        // 2*LAT
#define NUM_LAYERS 3

// Scratch (device globals; no allocations allowed)
__device__ float g_h[BB * NN * HID];     // 16 MB
__device__ float g_msg[BB * NN * HID];   // 16 MB

// ----------------------------------------------------------------------------
// Row-wise small GEMM: C[rows, OUT] = act( A[rows, K] @ W[K, OUT] (+bias) ) (*mask)
// 256 threads, 32 rows/block. K-chunked smem staging of W and A.
// Thread t owns row r = t>>3 and columns {cg + 8*j}, cg = t&7 (conflict-free sW reads,
// full-sector stores).
// ----------------------------------------------------------------------------
template<int K, int OUT, bool HAS_BIAS, bool HAS_MASK>
__global__ __launch_bounds__(256) void rowgemm_kernel(
    const float* __restrict__ A, const float* __restrict__ W,
    const float* __restrict__ bias, const float* __restrict__ mask,
    float* __restrict__ C)
{
    constexpr int ROWS = 32;
    constexpr int CPT = OUT / 8;   // columns per thread
    __shared__ float sW[32][OUT];
    __shared__ float sA[ROWS][33]; // +1 pad: conflict-free row broadcast

    const int tid = threadIdx.x;
    const int r   = tid >> 3;
    const int cg  = tid & 7;
    const int row0 = blockIdx.x * ROWS;

    float acc[CPT];
#pragma unroll
    for (int j = 0; j < CPT; j++) acc[j] = 0.f;

    for (int kc = 0; kc < K; kc += 32) {
        // stage W chunk [32, OUT]
        for (int idx = tid; idx < 32 * OUT; idx += 256) {
            int kk = idx / OUT, cc = idx % OUT;
            sW[kk][cc] = W[(kc + kk) * OUT + cc];
        }
        // stage A chunk [ROWS, 32]
        for (int idx = tid; idx < ROWS * 32; idx += 256) {
            int rr = idx >> 5, kk = idx & 31;
            sA[rr][kk] = A[(size_t)(row0 + rr) * K + kc + kk];
        }
        __syncthreads();
#pragma unroll
        for (int k = 0; k < 32; k++) {
            float a = sA[r][k];
#pragma unroll
            for (int j = 0; j < CPT; j++)
                acc[j] += a * sW[k][cg + 8 * j];
        }
        __syncthreads();
    }

    const int row = row0 + r;
    float m = 1.f;
    if (HAS_MASK) m = mask[row];
#pragma unroll
    for (int j = 0; j < CPT; j++) {
        float v = acc[j];
        if (HAS_BIAS) v += bias[cg + 8 * j];
        if (HAS_MASK) v *= m;
        C[(size_t)row * OUT + cg + 8 * j] = v;
    }
}

// ----------------------------------------------------------------------------
// Big batched GEMM + ReLU:  h[b] = relu( adj[b] (1024x1024) @ msg[b] (1024x128) )
// BM=128, BN=128, BK=16, 256 threads, 8x8 microtile. grid = (8 row tiles, 32 batches).
// 256 blocks @ 2 blocks/SM -> single wave on 148 SMs.
// ----------------------------------------------------------------------------
__global__ __launch_bounds__(256, 2) void adj_gemm_relu_kernel(
    const float* __restrict__ adj, const float* __restrict__ Bm,
    float* __restrict__ C)
{
    constexpr int BM = 128, BN = 128, BK = 16;
    __shared__ float As[BK][BM + 4];   // stride 132: breaks transpose-store conflicts
    __shared__ float Bs[BK][BN];

    const int b = blockIdx.y;
    const float* A  = adj + (size_t)b * NN * NN;
    const float* B  = Bm  + (size_t)b * NN * HID;
    float*       Cc = C   + (size_t)b * NN * HID;

    const int tid = threadIdx.x;
    const int tx = tid & 15;        // 0..15 -> cols tx*8..
    const int ty = tid >> 4;        // 0..15 -> rows ty*8..
    const int row0 = blockIdx.x * BM;

    float acc[8][8];
#pragma unroll
    for (int i = 0; i < 8; i++)
#pragma unroll
        for (int j = 0; j < 8; j++) acc[i][j] = 0.f;

    for (int k0 = 0; k0 < NN; k0 += BK) {
        // load A tile: 128 rows x 16 k  (512 float4, 2 per thread), store transposed
#pragma unroll
        for (int i = 0; i < 2; i++) {
            int f  = tid + i * 256;
            int m  = f >> 2;
            int kq = f & 3;
            float4 v = *reinterpret_cast<const float4*>(
                &A[(size_t)(row0 + m) * NN + k0 + kq * 4]);
            As[kq * 4 + 0][m] = v.x;
            As[kq * 4 + 1][m] = v.y;
            As[kq * 4 + 2][m] = v.z;
            As[kq * 4 + 3][m] = v.w;
        }
        // load B tile: 16 k x 128 n (512 float4, 2 per thread)
#pragma unroll
        for (int i = 0; i < 2; i++) {
            int f  = tid + i * 256;
            int kk = f >> 5;
            int nq = f & 31;
            *reinterpret_cast<float4*>(&Bs[kk][nq * 4]) =
                *reinterpret_cast<const float4*>(&B[(size_t)(k0 + kk) * HID + nq * 4]);
        }
        __syncthreads();

#pragma unroll
        for (int k = 0; k < BK; k++) {
            float ra[8], rb[8];
#pragma unroll
            for (int i = 0; i < 8; i++) ra[i] = As[k][ty * 8 + i];
#pragma unroll
            for (int j = 0; j < 8; j++) rb[j] = Bs[k][tx * 8 + j];
#pragma unroll
            for (int i = 0; i < 8; i++)
#pragma unroll
                for (int j = 0; j < 8; j++)
                    acc[i][j] += ra[i] * rb[j];
        }
        __syncthreads();
    }

    // epilogue: ReLU + vectorized store
#pragma unroll
    for (int i = 0; i < 8; i++) {
        int m = row0 + ty * 8 + i;
#pragma unroll
        for (int j = 0; j < 8; j += 4) {
            float4 v;
            v.x = fmaxf(acc[i][j + 0], 0.f);
            v.y = fmaxf(acc[i][j + 1], 0.f);
            v.z = fmaxf(acc[i][j + 2], 0.f);
            v.w = fmaxf(acc[i][j + 3], 0.f);
            *reinterpret_cast<float4*>(&Cc[(size_t)m * HID + tx * 8 + j]) = v;
        }
    }
}

// ----------------------------------------------------------------------------
// Launch
// Inputs (metadata order):
//   0: node_features   [B, N, 64]   f32
//   1: adjacency_matrix[B, N, N]    f32
//   2: node_mask       [B, N, 1]    f32
//   3: W_embed         [64, 128]    f32
//   4: Wl              [3, 128, 128]f32
//   5: bl              [3, 128]     f32
//   6: W_proj          [128, 64]    f32
//   7: b_proj          [64]         f32
// Output: [B, N, 64] f32
// ----------------------------------------------------------------------------
extern "C" void kernel_launch(void* const* d_in, const int* in_sizes, int n_in,
                              void* d_out, int out_size)
{
    const float* x      = (const float*)d_in[0];
    const float* adj    = (const float*)d_in[1];
    const float* mask   = (const float*)d_in[2];
    const float* Wemb   = (const float*)d_in[3];
    const float* Wl     = (const float*)d_in[4];
    const float* bl     = (const float*)d_in[5];
    const float* Wproj  = (const float*)d_in[6];
    const float* bproj  = (const float*)d_in[7];
    float* out = (float*)d_out;

    float *h_ptr = nullptr, *msg_ptr = nullptr;
    cudaGetSymbolAddress((void**)&h_ptr, g_h);
    cudaGetSymbolAddress((void**)&msg_ptr, g_msg);

    const int nrows = BB * NN;                 // 32768
    dim3 rowgrid(nrows / 32);                  // 1024 blocks

    // 1) embed: h = x @ W_embed   (no bias)
    rowgemm_kernel<IN_DIM, HID, false, false><<<rowgrid, 256>>>(
        x, Wemb, nullptr, nullptr, h_ptr);

    // 2) GCN layers
    dim3 bigg(NN / 128, BB);                   // (8, 32) = 256 blocks
    for (int l = 0; l < NUM_LAYERS; l++) {
        rowgemm_kernel<HID, HID, true, false><<<rowgrid, 256>>>(
            h_ptr, Wl + (size_t)l * HID * HID, bl + (size_t)l * HID, nullptr, msg_ptr);
        adj_gemm_relu_kernel<<<bigg, 256>>>(adj, msg_ptr, h_ptr);
    }

    // 3) projection + mask: out = (h @ W_proj + b_proj) * mask
    rowgemm_kernel<HID, OUTD, true, true><<<rowgrid, 256>>>(
        h_ptr, Wproj, bproj, mask, out);
}